// round 14
// baseline (speedup 1.0000x reference)
#include <cuda_runtime.h>
#include <math.h>
#include <stdint.h>

#define TSEQ 2048
#define CEMB 2048
#define BATCH 2
#define NHEAD 16
#define NGRP 4
#define HD 128
#define QKVN 3072          // (16 + 2*4) * 128
#define FFN 8192
#define MROWS 4096         // B*T
#define SCALE 0.08838834764831845f  // 1/sqrt(128)

// ---------------- scratch (device globals: allocation-free rule) -------------
__device__ float g_xn1[MROWS * CEMB];
__device__ float g_xn2[MROWS * CEMB];
__device__ float g_qkv[MROWS * QKVN];
__device__ float g_y  [MROWS * CEMB];
__device__ float g_act[(size_t)MROWS * FFN];
__device__ float g_scores[(size_t)BATCH * NHEAD * TSEQ * TSEQ];
__device__ float g_wcvt[44040192];   // tf32-rounded TRANSPOSED weights
__device__ float g_vt[(size_t)BATCH * NGRP * HD * TSEQ];  // V transposed [b*g][d][s]

// ---------------- tf32 / mma / cp.async helpers ------------------------------
__device__ __forceinline__ float to_tf32(float x) {
    asm("cvt.rna.tf32.f32 %0, %0;" : "+f"(x));
    return x;
}

__device__ __forceinline__ void mma8(float c[4], const uint32_t a[4], const uint32_t b[2]) {
    asm volatile(
        "mma.sync.aligned.m16n8k8.row.col.f32.tf32.tf32.f32 "
        "{%0,%1,%2,%3}, {%4,%5,%6,%7}, {%8,%9}, {%0,%1,%2,%3};\n"
        : "+f"(c[0]), "+f"(c[1]), "+f"(c[2]), "+f"(c[3])
        : "r"(a[0]), "r"(a[1]), "r"(a[2]), "r"(a[3]), "r"(b[0]), "r"(b[1]));
}

__device__ __forceinline__ void cp16(uint32_t dst, const void* src) {
    asm volatile("cp.async.cg.shared.global [%0], [%1], 16;" :: "r"(dst), "l"(src));
}
__device__ __forceinline__ void cp_commit() { asm volatile("cp.async.commit_group;"); }
__device__ __forceinline__ void cp_wait2()  { asm volatile("cp.async.wait_group 2;"); }

// ---------------- weight tf32 round + transpose [K][N] -> [N][K] -------------
__global__ void __launch_bounds__(256) wtrans_kernel(
    const float* __restrict__ in, float* __restrict__ outp, int K, int N)
{
    __shared__ float t[32][33];
    int nb = blockIdx.x * 32, kb = blockIdx.y * 32;
    int tx = threadIdx.x & 31, ty = threadIdx.x >> 5;
    #pragma unroll
    for (int i = 0; i < 4; i++)
        t[ty + i*8][tx] = in[(size_t)(kb + ty + i*8) * N + nb + tx];
    __syncthreads();
    #pragma unroll
    for (int i = 0; i < 4; i++)
        outp[(size_t)(nb + ty + i*8) * K + kb + tx] = to_tf32(t[tx][ty + i*8]);
}

// ---------------- V transpose: g_qkv v-slices -> g_vt[bg][d][s] --------------
__global__ void __launch_bounds__(256) vtrans_kernel()
{
    __shared__ float t[32][33];
    int z = blockIdx.z;
    int b = z >> 2, g = z & 3;
    int sb = blockIdx.x * 32, db = blockIdx.y * 32;
    int tx = threadIdx.x & 31, ty = threadIdx.x >> 5;
    #pragma unroll
    for (int i = 0; i < 4; i++)
        t[ty + i*8][tx] = g_qkv[(size_t)(b*TSEQ + sb + ty + i*8) * QKVN + g*768 + 640 + db + tx];
    __syncthreads();
    #pragma unroll
    for (int i = 0; i < 4; i++)
        g_vt[((size_t)z * HD + db + ty + i*8) * TSEQ + sb + tx] = t[tx][ty + i*8];
}

// ---------------- fused double LayerNorm (tf32-rounded outputs) --------------
__global__ void __launch_bounds__(256) ln_kernel(
    const float* __restrict__ x,
    const float* __restrict__ w1, const float* __restrict__ b1,
    const float* __restrict__ w2, const float* __restrict__ b2)
{
    int row = blockIdx.x, tid = threadIdx.x;
    const float4* xr = (const float4*)(x + (size_t)row * CEMB);
    float4 a = xr[tid], b = xr[tid + 256];

    float s = a.x + a.y + a.z + a.w + b.x + b.y + b.z + b.w;
    float q = a.x*a.x + a.y*a.y + a.z*a.z + a.w*a.w
            + b.x*b.x + b.y*b.y + b.z*b.z + b.w*b.w;
    #pragma unroll
    for (int o = 16; o; o >>= 1) {
        s += __shfl_xor_sync(0xffffffffu, s, o);
        q += __shfl_xor_sync(0xffffffffu, q, o);
    }
    __shared__ float rs[8], rq[8], s_mu, s_rstd;
    int wid = tid >> 5, lane = tid & 31;
    if (!lane) { rs[wid] = s; rq[wid] = q; }
    __syncthreads();
    if (tid == 0) {
        float S = 0.f, Q = 0.f;
        #pragma unroll
        for (int i = 0; i < 8; i++) { S += rs[i]; Q += rq[i]; }
        float mu  = S * (1.0f / CEMB);
        float var = Q * (1.0f / CEMB) - mu * mu;
        s_mu = mu;
        s_rstd = rsqrtf(var + 1e-5f);
    }
    __syncthreads();
    float mu = s_mu, r = s_rstd;

    const float4* W1 = (const float4*)w1; const float4* B1 = (const float4*)b1;
    const float4* W2 = (const float4*)w2; const float4* B2 = (const float4*)b2;
    float4* o1 = (float4*)(g_xn1 + (size_t)row * CEMB);
    float4* o2 = (float4*)(g_xn2 + (size_t)row * CEMB);

    float4 w1a = W1[tid], w1b = W1[tid+256], b1a = B1[tid], b1b = B1[tid+256];
    float4 w2a = W2[tid], w2b = W2[tid+256], b2a = B2[tid], b2b = B2[tid+256];

    float4 na, nb;
    na.x = (a.x-mu)*r; na.y = (a.y-mu)*r; na.z = (a.z-mu)*r; na.w = (a.w-mu)*r;
    nb.x = (b.x-mu)*r; nb.y = (b.y-mu)*r; nb.z = (b.z-mu)*r; nb.w = (b.w-mu)*r;

    float4 t;
    t.x = to_tf32(na.x*w1a.x+b1a.x); t.y = to_tf32(na.y*w1a.y+b1a.y);
    t.z = to_tf32(na.z*w1a.z+b1a.z); t.w = to_tf32(na.w*w1a.w+b1a.w);
    o1[tid] = t;
    t.x = to_tf32(nb.x*w1b.x+b1b.x); t.y = to_tf32(nb.y*w1b.y+b1b.y);
    t.z = to_tf32(nb.z*w1b.z+b1b.z); t.w = to_tf32(nb.w*w1b.w+b1b.w);
    o1[tid+256] = t;
    t.x = to_tf32(na.x*w2a.x+b2a.x); t.y = to_tf32(na.y*w2a.y+b2a.y);
    t.z = to_tf32(na.z*w2a.z+b2a.z); t.w = to_tf32(na.w*w2a.w+b2a.w);
    o2[tid] = t;
    t.x = to_tf32(nb.x*w2b.x+b2b.x); t.y = to_tf32(nb.y*w2b.y+b2b.y);
    t.z = to_tf32(nb.z*w2b.z+b2b.z); t.w = to_tf32(nb.w*w2b.w+b2b.w);
    o2[tid+256] = t;
}

// ---------------- RoPE (in-place, tf32-rounded outputs) ----------------------
__global__ void __launch_bounds__(320) rope_kernel(
    const float* __restrict__ cosb, const float* __restrict__ sinb)
{
    int row = blockIdx.x;
    int t   = row & (TSEQ - 1);
    int tid = threadIdx.x;
    int head = tid >> 4;
    int i    = tid & 15;

    float* base;
    if (head < 16) {
        int g = head >> 2, slot = head & 3;
        base = g_qkv + (size_t)row * QKVN + g * 768 + slot * 128;
    } else {
        int g = head - 16;
        base = g_qkv + (size_t)row * QKVN + g * 768 + 512;
    }
    float c1 = cosb[t*32 + i],      s1 = sinb[t*32 + i];
    float c2 = cosb[t*32 + i + 16], s2 = sinb[t*32 + i + 16];
    float x1 = base[i], x2 = base[i + 16];
    base[i]      = to_tf32(x1 * c1 - x2 * s1);
    base[i + 16] = to_tf32(x2 * c2 + x1 * s2);
}

// ======================= 128x256 tf32 GEMM (mma.sync) ========================
// 256 threads = 8 warps (2M x 4N), warp tile 64x64, acc 128 regs/thread.
// A smem m-major [128][16], B smem n-major [256][16]; pitch 16 -> LDS.128
// conflict-free. k-permutation as R11 (A and B agree on k-slot mapping).
// cp.async 4-stage, issue 2 ahead, one __syncthreads per iter.

enum { EPI_CVT = 0, EPI_RESID = 1, EPI_GELU = 2, EPI_ADDOUT = 3 };

#define G_ASTN 2048          // A floats per stage (128*16)
#define G_STG  6144          // A + B floats per stage (+256*16) = 24576 B
#define G_SMEM (4 * G_STG * 4)   // 98304 B

__device__ __forceinline__ void stage_mma256(
    const float* As, const float* Bs, int wm, int wn, int lr, int lc,
    float acc[4][8][4])
{
    float4 bv[8];
    #pragma unroll
    for (int ntt = 0; ntt < 8; ntt++)
        bv[ntt] = *(const float4*)&Bs[(wn + ntt*8 + lr)*16 + lc*4];
    #pragma unroll
    for (int mt = 0; mt < 4; mt++) {
        float4 alo = *(const float4*)&As[(wm + mt*16 + lr)*16 + lc*4];
        float4 ahi = *(const float4*)&As[(wm + mt*16 + 8 + lr)*16 + lc*4];
        uint32_t a0[4] = { __float_as_uint(alo.x), __float_as_uint(ahi.x),
                           __float_as_uint(alo.y), __float_as_uint(ahi.y) };
        uint32_t a1[4] = { __float_as_uint(alo.z), __float_as_uint(ahi.z),
                           __float_as_uint(alo.w), __float_as_uint(ahi.w) };
        #pragma unroll
        for (int ntt = 0; ntt < 8; ntt++) {
            uint32_t b0[2] = { __float_as_uint(bv[ntt].x), __float_as_uint(bv[ntt].y) };
            mma8(acc[mt][ntt], a0, b0);
        }
        #pragma unroll
        for (int ntt = 0; ntt < 8; ntt++) {
            uint32_t b1[2] = { __float_as_uint(bv[ntt].z), __float_as_uint(bv[ntt].w) };
            mma8(acc[mt][ntt], a1, b1);
        }
    }
}

template<int EPI>
__global__ void __launch_bounds__(256, 1) mm_pipe(
    const float* __restrict__ A,      // [M][K] row-major, tf32-rounded
    const float* __restrict__ Bt,     // [N][K] row-major (transposed weights)
    float* __restrict__ C, int ldc,
    const float* __restrict__ bias,
    const float* __restrict__ resid,
    int K)
{
    extern __shared__ float sm[];
    const int tid = threadIdx.x, lane = tid & 31, wid = tid >> 5;
    const int wm = (wid >> 2) * 64, wn = (wid & 3) * 64;
    const int lr = lane >> 2, lc = lane & 3;
    const int m0 = blockIdx.y * 128, n0 = blockIdx.x * 256;
    const uint32_t smb = (uint32_t)__cvta_generic_to_shared(sm);

    // 6 cp.async granules (16B) per thread per k16: 512 for A, 1024 for B
    const float* src[6]; uint32_t dst[6];
    #pragma unroll
    for (int j = 0; j < 6; j++) {
        int g = tid + j * 256;
        if (g < 512) {
            int r = g >> 2, gc = (g & 3) * 4;
            src[j] = A + (size_t)(m0 + r) * K + gc;
            dst[j] = (uint32_t)(r*16 + gc) * 4;
        } else {
            int gb = g - 512, r = gb >> 2, gc = (gb & 3) * 4;
            src[j] = Bt + (size_t)(n0 + r) * K + gc;
            dst[j] = (uint32_t)(G_ASTN + r*16 + gc) * 4;
        }
    }

    const int nt = K >> 4;
    auto issue = [&](int i) {
        uint32_t so = smb + (uint32_t)(i & 3) * (G_STG * 4);
        int k0 = i << 4;
        #pragma unroll
        for (int j = 0; j < 6; j++) cp16(so + dst[j], src[j] + k0);
    };
    issue(0); cp_commit();
    issue(1); cp_commit();

    float acc[4][8][4];
    #pragma unroll
    for (int mt = 0; mt < 4; mt++)
        #pragma unroll
        for (int ntt = 0; ntt < 8; ntt++)
            #pragma unroll
            for (int i = 0; i < 4; i++) acc[mt][ntt][i] = 0.f;

    for (int i = 0; i < nt; i++) {
        if (i + 2 < nt) issue(i + 2);
        cp_commit();
        cp_wait2();
        __syncthreads();
        const float* As = sm + (size_t)(i & 3) * G_STG;
        stage_mma256(As, As + G_ASTN, wm, wn, lr, lc, acc);
    }

    #pragma unroll
    for (int mt = 0; mt < 4; mt++) {
        int r = m0 + wm + mt*16 + lr;
        #pragma unroll
        for (int ntt = 0; ntt < 8; ntt++) {
            int cn = n0 + wn + ntt*8 + lc*2;
            float bx = bias[cn], by = bias[cn+1];
            float* p0 = C + (size_t)r * ldc + cn;
            float* p1 = C + (size_t)(r+8) * ldc + cn;
            float v0 = acc[mt][ntt][0] + bx, v1 = acc[mt][ntt][1] + by;
            float v2 = acc[mt][ntt][2] + bx, v3 = acc[mt][ntt][3] + by;
            if (EPI == EPI_RESID) {
                const float* q0 = resid + (size_t)r * ldc + cn;
                const float* q1 = resid + (size_t)(r+8) * ldc + cn;
                v0 += q0[0]; v1 += q0[1]; v2 += q1[0]; v3 += q1[1];
            }
            if (EPI == EPI_GELU) {
                v0 = to_tf32(0.5f*v0*(1.0f + erff(v0*0.70710678118654752f)));
                v1 = to_tf32(0.5f*v1*(1.0f + erff(v1*0.70710678118654752f)));
                v2 = to_tf32(0.5f*v2*(1.0f + erff(v2*0.70710678118654752f)));
                v3 = to_tf32(0.5f*v3*(1.0f + erff(v3*0.70710678118654752f)));
            }
            if (EPI == EPI_ADDOUT) { v0 += p0[0]; v1 += p0[1]; v2 += p1[0]; v3 += p1[1]; }
            if (EPI == EPI_CVT) { v0 = to_tf32(v0); v1 = to_tf32(v1); v2 = to_tf32(v2); v3 = to_tf32(v3); }
            p0[0] = v0; p0[1] = v1; p1[0] = v2; p1[1] = v3;
        }
    }
}

// ======================= mma.sync attention (R11-proven) =====================
#define ASTN 2048
#define STG  4096
#define MM_SMEM (4 * STG * 4)

__device__ __forceinline__ void stage_mma(
    const float* As, const float* Bs, int wm, int wn, int lr, int lc,
    float acc[4][4][4])
{
    float4 bv[4];
    #pragma unroll
    for (int ntt = 0; ntt < 4; ntt++)
        bv[ntt] = *(const float4*)&Bs[(wn + ntt*8 + lr)*16 + lc*4];
    #pragma unroll
    for (int mt = 0; mt < 4; mt++) {
        float4 alo = *(const float4*)&As[(wm + mt*16 + lr)*16 + lc*4];
        float4 ahi = *(const float4*)&As[(wm + mt*16 + 8 + lr)*16 + lc*4];
        uint32_t a0[4] = { __float_as_uint(alo.x), __float_as_uint(ahi.x),
                           __float_as_uint(alo.y), __float_as_uint(ahi.y) };
        uint32_t a1[4] = { __float_as_uint(alo.z), __float_as_uint(ahi.z),
                           __float_as_uint(alo.w), __float_as_uint(ahi.w) };
        #pragma unroll
        for (int ntt = 0; ntt < 4; ntt++) {
            uint32_t b0[2] = { __float_as_uint(bv[ntt].x), __float_as_uint(bv[ntt].y) };
            mma8(acc[mt][ntt], a0, b0);
        }
        #pragma unroll
        for (int ntt = 0; ntt < 4; ntt++) {
            uint32_t b1[2] = { __float_as_uint(bv[ntt].z), __float_as_uint(bv[ntt].w) };
            mma8(acc[mt][ntt], a1, b1);
        }
    }
}

__global__ void __launch_bounds__(256, 2) attn_scores_mma()
{
    int si = blockIdx.x, ti = blockIdx.y;
    if (si > ti) return;
    int bh = blockIdx.z;
    int b = bh >> 4, h = bh & 15, g = h >> 2, sl = h & 3;

    const float* Q  = g_qkv + (size_t)b*TSEQ*QKVN + g*768 + sl*128 + (size_t)ti*128*QKVN;
    const float* Kp = g_qkv + (size_t)b*TSEQ*QKVN + g*768 + 512    + (size_t)si*128*QKVN;

    extern __shared__ float sm[];
    const int tid = threadIdx.x, lane = tid & 31, wid = tid >> 5;
    const int wm = (wid >> 2) * 64, wn = (wid & 3) * 32;
    const int lr = lane >> 2, lc = lane & 3;
    const uint32_t smb = (uint32_t)__cvta_generic_to_shared(sm);

    const int r0 = tid >> 2,        cq0 = (tid & 3) * 4;
    const int r1 = (tid + 256) >> 2;
    const float* Asrc0 = Q  + (size_t)r0 * QKVN + cq0;
    const float* Asrc1 = Q  + (size_t)r1 * QKVN + cq0;
    const float* Bsrc0 = Kp + (size_t)r0 * QKVN + cq0;
    const float* Bsrc1 = Kp + (size_t)r1 * QKVN + cq0;
    const uint32_t Ad0 = smb + (uint32_t)(r0*16 + cq0) * 4;
    const uint32_t Ad1 = smb + (uint32_t)(r1*16 + cq0) * 4;
    const uint32_t Bd0 = smb + (uint32_t)(ASTN + r0*16 + cq0) * 4;
    const uint32_t Bd1 = smb + (uint32_t)(ASTN + r1*16 + cq0) * 4;

    auto issue = [&](int i) {
        uint32_t so = (uint32_t)(i & 3) * (STG * 4);
        int k0 = i << 4;
        cp16(Ad0 + so, Asrc0 + k0);
        cp16(Ad1 + so, Asrc1 + k0);
        cp16(Bd0 + so, Bsrc0 + k0);
        cp16(Bd1 + so, Bsrc1 + k0);
    };
    issue(0); cp_commit();
    issue(1); cp_commit();

    float acc[4][4][4];
    #pragma unroll
    for (int mt = 0; mt < 4; mt++)
        #pragma unroll
        for (int ntt = 0; ntt < 4; ntt++)
            #pragma unroll
            for (int i = 0; i < 4; i++) acc[mt][ntt][i] = 0.f;

    for (int i = 0; i < 8; i++) {
        if (i + 2 < 8) issue(i + 2);
        cp_commit();
        cp_wait2();
        __syncthreads();
        const float* As = sm + (size_t)(i & 3) * STG;
        stage_mma(As, As + ASTN, wm, wn, lr, lc, acc);
    }

    float* S = g_scores + (size_t)bh * TSEQ * TSEQ;
    #pragma unroll
    for (int mt = 0; mt < 4; mt++) {
        int t0 = ti*128 + wm + mt*16 + lr;
        int t1 = t0 + 8;
        #pragma unroll
        for (int ntt = 0; ntt < 4; ntt++) {
            int s0 = si*128 + wn + ntt*8 + lc*2;
            S[(size_t)t0*TSEQ + s0  ] = (s0   <= t0) ? acc[mt][ntt][0]*SCALE : -3.0e38f;
            S[(size_t)t0*TSEQ + s0+1] = (s0+1 <= t0) ? acc[mt][ntt][1]*SCALE : -3.0e38f;
            S[(size_t)t1*TSEQ + s0  ] = (s0   <= t1) ? acc[mt][ntt][2]*SCALE : -3.0e38f;
            S[(size_t)t1*TSEQ + s0+1] = (s0+1 <= t1) ? acc[mt][ntt][3]*SCALE : -3.0e38f;
        }
    }
}

__global__ void __launch_bounds__(128) softmax_kernel()
{
    int t = blockIdx.x, bh = blockIdx.y;
    float* row = g_scores + ((size_t)bh * TSEQ + t) * TSEQ;
    int cnt = (t >> 7) + 1;
    int tid = threadIdx.x;

    float v[16];
    float mx = -3.4e38f;
    #pragma unroll
    for (int c = 0; c < 16; c++)
        if (c < cnt) { v[c] = row[c*128 + tid]; mx = fmaxf(mx, v[c]); }
    #pragma unroll
    for (int o = 16; o; o >>= 1) mx = fmaxf(mx, __shfl_xor_sync(0xffffffffu, mx, o));

    __shared__ float sm1[4], sm2[4];
    int wid = tid >> 5, lane = tid & 31;
    if (!lane) sm1[wid] = mx;
    __syncthreads();
    mx = fmaxf(fmaxf(sm1[0], sm1[1]), fmaxf(sm1[2], sm1[3]));

    float s = 0.f;
    #pragma unroll
    for (int c = 0; c < 16; c++)
        if (c < cnt) { v[c] = __expf(v[c] - mx); s += v[c]; }
    #pragma unroll
    for (int o = 16; o; o >>= 1) s += __shfl_xor_sync(0xffffffffu, s, o);
    if (!lane) sm2[wid] = s;
    __syncthreads();
    s = sm2[0] + sm2[1] + sm2[2] + sm2[3];

    float inv = 1.0f / s;
    #pragma unroll
    for (int c = 0; c < 16; c++)
        if (c < cnt) row[c*128 + tid] = to_tf32(v[c] * inv);
}

__global__ void __launch_bounds__(256, 2) attn_av_mma()
{
    int ti = blockIdx.x, bh = blockIdx.y;
    int b = bh >> 4, h = bh & 15, g = h >> 2;

    const float* P  = g_scores + (size_t)bh * TSEQ * TSEQ + (size_t)ti*128 * TSEQ;
    const float* Vt = g_vt + (size_t)(b*NGRP + g) * HD * TSEQ;

    extern __shared__ float sm[];
    const int tid = threadIdx.x, lane = tid & 31, wid = tid >> 5;
    const int wm = (wid >> 2) * 64, wn = (wid & 3) * 32;
    const int lr = lane >> 2, lc = lane & 3;
    const uint32_t smb = (uint32_t)__cvta_generic_to_shared(sm);

    const int r0 = tid >> 2,        cq0 = (tid & 3) * 4;
    const int r1 = (tid + 256) >> 2;
    const float* Asrc0 = P  + (size_t)r0 * TSEQ + cq0;
    const float* Asrc1 = P  + (size_t)r1 * TSEQ + cq0;
    const float* Bsrc0 = Vt + (size_t)r0 * TSEQ + cq0;
    const float* Bsrc1 = Vt + (size_t)r1 * TSEQ + cq0;
    const uint32_t Ad0 = smb + (uint32_t)(r0*16 + cq0) * 4;
    const uint32_t Ad1 = smb + (uint32_t)(r1*16 + cq0) * 4;
    const uint32_t Bd0 = smb + (uint32_t)(ASTN + r0*16 + cq0) * 4;
    const uint32_t Bd1 = smb + (uint32_t)(ASTN + r1*16 + cq0) * 4;

    const int nt = (ti + 1) * 8;
    auto issue = [&](int i) {
        uint32_t so = (uint32_t)(i & 3) * (STG * 4);
        int k0 = i << 4;
        cp16(Ad0 + so, Asrc0 + k0);
        cp16(Ad1 + so, Asrc1 + k0);
        cp16(Bd0 + so, Bsrc0 + k0);
        cp16(Bd1 + so, Bsrc1 + k0);
    };
    issue(0); cp_commit();
    issue(1); cp_commit();

    float acc[4][4][4];
    #pragma unroll
    for (int mt = 0; mt < 4; mt++)
        #pragma unroll
        for (int ntt = 0; ntt < 4; ntt++)
            #pragma unroll
            for (int i = 0; i < 4; i++) acc[mt][ntt][i] = 0.f;

    for (int i = 0; i < nt; i++) {
        if (i + 2 < nt) issue(i + 2);
        cp_commit();
        cp_wait2();
        __syncthreads();
        const float* As = sm + (size_t)(i & 3) * STG;
        stage_mma(As, As + ASTN, wm, wn, lr, lc, acc);
    }

    float* Y = g_y + (size_t)(b*TSEQ + ti*128) * CEMB + h*128;
    #pragma unroll
    for (int mt = 0; mt < 4; mt++) {
        int rr = wm + mt*16 + lr;
        #pragma unroll
        for (int ntt = 0; ntt < 4; ntt++) {
            int dd = wn + ntt*8 + lc*2;
            Y[(size_t)rr*CEMB + dd  ]     = to_tf32(acc[mt][ntt][0]);
            Y[(size_t)rr*CEMB + dd+1]     = to_tf32(acc[mt][ntt][1]);
            Y[(size_t)(rr+8)*CEMB + dd  ] = to_tf32(acc[mt][ntt][2]);
            Y[(size_t)(rr+8)*CEMB + dd+1] = to_tf32(acc[mt][ntt][3]);
        }
    }
}

// ---------------- launch ----------------------------------------------------
extern "C" void kernel_launch(void* const* d_in, const int* in_sizes, int n_in,
                              void* d_out, int out_size)
{
    (void)in_sizes; (void)n_in; (void)out_size;
    const float* x     = (const float*)d_in[0];
    const float* cosb  = (const float*)d_in[1];
    const float* sinb  = (const float*)d_in[2];
    const float* ln1w  = (const float*)d_in[3];
    const float* ln1b  = (const float*)d_in[4];
    const float* wqkv  = (const float*)d_in[5];
    const float* bqkv  = (const float*)d_in[6];
    const float* wproj = (const float*)d_in[7];
    const float* bproj = (const float*)d_in[8];
    const float* ln2w  = (const float*)d_in[9];
    const float* ln2b  = (const float*)d_in[10];
    const float* wfc1  = (const float*)d_in[11];
    const float* bfc1  = (const float*)d_in[12];
    const float* wfc2  = (const float*)d_in[13];
    const float* bfc2  = (const float*)d_in[14];
    float* out = (float*)d_out;

    float *xn1, *xn2, *qkv, *yv, *act, *wc;
    cudaGetSymbolAddress((void**)&xn1, g_xn1);
    cudaGetSymbolAddress((void**)&xn2, g_xn2);
    cudaGetSymbolAddress((void**)&qkv, g_qkv);
    cudaGetSymbolAddress((void**)&yv,  g_y);
    cudaGetSymbolAddress((void**)&act, g_act);
    cudaGetSymbolAddress((void**)&wc,  g_wcvt);
    float* wqkv_t  = wc;                 // [3072][2048]
    float* wproj_t = wc + 6291456;       // [2048][2048]
    float* wfc1_t  = wc + 10485760;      // [8192][2048]
    float* wfc2_t  = wc + 27262976;      // [2048][8192]

    cudaFuncSetAttribute(mm_pipe<EPI_CVT>,    cudaFuncAttributeMaxDynamicSharedMemorySize, G_SMEM);
    cudaFuncSetAttribute(mm_pipe<EPI_RESID>,  cudaFuncAttributeMaxDynamicSharedMemorySize, G_SMEM);
    cudaFuncSetAttribute(mm_pipe<EPI_GELU>,   cudaFuncAttributeMaxDynamicSharedMemorySize, G_SMEM);
    cudaFuncSetAttribute(mm_pipe<EPI_ADDOUT>, cudaFuncAttributeMaxDynamicSharedMemorySize, G_SMEM);
    cudaFuncSetAttribute(attn_scores_mma,     cudaFuncAttributeMaxDynamicSharedMemorySize, MM_SMEM);
    cudaFuncSetAttribute(attn_av_mma,         cudaFuncAttributeMaxDynamicSharedMemorySize, MM_SMEM);

    // 0. tf32-round + transpose all weights to [N][K]
    wtrans_kernel<<<dim3(QKVN/32, CEMB/32), 256>>>(wqkv,  wqkv_t,  CEMB, QKVN);
    wtrans_kernel<<<dim3(CEMB/32, CEMB/32), 256>>>(wproj, wproj_t, CEMB, CEMB);
    wtrans_kernel<<<dim3(FFN/32,  CEMB/32), 256>>>(wfc1,  wfc1_t,  CEMB, FFN);
    wtrans_kernel<<<dim3(CEMB/32, FFN/32),  256>>>(wfc2,  wfc2_t,  FFN,  CEMB);

    // 1. LN1 + LN2 (shared statistics, tf32-rounded outputs)
    ln_kernel<<<MROWS, 256>>>(x, ln1w, ln1b, ln2w, ln2b);

    // 2. QKV GEMM (128x256 tiles)
    mm_pipe<EPI_CVT><<<dim3(QKVN/256, MROWS/128), 256, G_SMEM>>>(
        xn1, wqkv_t, qkv, QKVN, bqkv, nullptr, CEMB);

    // 3. RoPE in-place, V transpose
    rope_kernel<<<MROWS, 320>>>(cosb, sinb);
    vtrans_kernel<<<dim3(TSEQ/32, HD/32, BATCH*NGRP), 256>>>();

    // 4-6. causal scores, softmax, P·V
    attn_scores_mma<<<dim3(16, 16, BATCH*NHEAD), 256, MM_SMEM>>>();
    softmax_kernel<<<dim3(TSEQ, BATCH*NHEAD), 128>>>();
    attn_av_mma<<<dim3(16, BATCH*NHEAD), 256, MM_SMEM>>>();

    // 7. proj GEMM (+b_proj + x residual) -> d_out
    mm_pipe<EPI_RESID><<<dim3(CEMB/256, MROWS/128), 256, G_SMEM>>>(
        yv, wproj_t, out, CEMB, bproj, x, CEMB);

    // 8. fc1 GEMM + exact GELU (tf32-rounded)
    mm_pipe<EPI_GELU><<<dim3(FFN/256, MROWS/128), 256, G_SMEM>>>(
        xn2, wfc1_t, act, FFN, bfc1, nullptr, CEMB);

    // 9. fc2 GEMM adds into d_out
    mm_pipe<EPI_ADDOUT><<<dim3(CEMB/256, MROWS/128), 256, G_SMEM>>>(
        act, wfc2_t, out, CEMB, bfc2, nullptr, FFN);
}

// round 15
// speedup vs baseline: 1.1139x; 1.1139x over previous
#include <cuda_runtime.h>
#include <math.h>
#include <stdint.h>

#define TSEQ 2048
#define CEMB 2048
#define BATCH 2
#define NHEAD 16
#define NGRP 4
#define HD 128
#define QKVN 3072          // (16 + 2*4) * 128
#define FFN 8192
#define MROWS 4096         // B*T
#define SCALE 0.08838834764831845f  // 1/sqrt(128)

// ---------------- scratch (device globals: allocation-free rule) -------------
__device__ float g_xn1[MROWS * CEMB];
__device__ float g_xn2[MROWS * CEMB];
__device__ float g_qkv[MROWS * QKVN];
__device__ float g_y  [MROWS * CEMB];
__device__ float g_act[(size_t)MROWS * FFN];
__device__ float g_scores[(size_t)BATCH * NHEAD * TSEQ * TSEQ];  // holds P_unnorm
__device__ float g_psum[(size_t)BATCH * NHEAD * TSEQ * 16];      // per-tile row sums
__device__ float g_wcvt[44040192];   // tf32-rounded TRANSPOSED weights
__device__ float g_vt[(size_t)BATCH * NGRP * HD * TSEQ];  // V transposed [b*g][d][s]

// ---------------- tf32 / mma / cp.async helpers ------------------------------
__device__ __forceinline__ float to_tf32(float x) {
    asm("cvt.rna.tf32.f32 %0, %0;" : "+f"(x));
    return x;
}

__device__ __forceinline__ void mma8(float c[4], const uint32_t a[4], const uint32_t b[2]) {
    asm volatile(
        "mma.sync.aligned.m16n8k8.row.col.f32.tf32.tf32.f32 "
        "{%0,%1,%2,%3}, {%4,%5,%6,%7}, {%8,%9}, {%0,%1,%2,%3};\n"
        : "+f"(c[0]), "+f"(c[1]), "+f"(c[2]), "+f"(c[3])
        : "r"(a[0]), "r"(a[1]), "r"(a[2]), "r"(a[3]), "r"(b[0]), "r"(b[1]));
}

__device__ __forceinline__ void cp16(uint32_t dst, const void* src) {
    asm volatile("cp.async.cg.shared.global [%0], [%1], 16;" :: "r"(dst), "l"(src));
}
__device__ __forceinline__ void cp_commit() { asm volatile("cp.async.commit_group;"); }
__device__ __forceinline__ void cp_wait2()  { asm volatile("cp.async.wait_group 2;"); }

// ---------------- weight tf32 round + transpose [K][N] -> [N][K] -------------
__global__ void __launch_bounds__(256) wtrans_kernel(
    const float* __restrict__ in, float* __restrict__ outp, int K, int N)
{
    __shared__ float t[32][33];
    int nb = blockIdx.x * 32, kb = blockIdx.y * 32;
    int tx = threadIdx.x & 31, ty = threadIdx.x >> 5;
    #pragma unroll
    for (int i = 0; i < 4; i++)
        t[ty + i*8][tx] = in[(size_t)(kb + ty + i*8) * N + nb + tx];
    __syncthreads();
    #pragma unroll
    for (int i = 0; i < 4; i++)
        outp[(size_t)(nb + ty + i*8) * K + kb + tx] = to_tf32(t[tx][ty + i*8]);
}

// ---------------- V transpose: g_qkv v-slices -> g_vt[bg][d][s] --------------
__global__ void __launch_bounds__(256) vtrans_kernel()
{
    __shared__ float t[32][33];
    int z = blockIdx.z;
    int b = z >> 2, g = z & 3;
    int sb = blockIdx.x * 32, db = blockIdx.y * 32;
    int tx = threadIdx.x & 31, ty = threadIdx.x >> 5;
    #pragma unroll
    for (int i = 0; i < 4; i++)
        t[ty + i*8][tx] = g_qkv[(size_t)(b*TSEQ + sb + ty + i*8) * QKVN + g*768 + 640 + db + tx];
    __syncthreads();
    #pragma unroll
    for (int i = 0; i < 4; i++)
        g_vt[((size_t)z * HD + db + ty + i*8) * TSEQ + sb + tx] = t[tx][ty + i*8];
}

// ---------------- fused double LayerNorm (tf32-rounded outputs) --------------
__global__ void __launch_bounds__(256) ln_kernel(
    const float* __restrict__ x,
    const float* __restrict__ w1, const float* __restrict__ b1,
    const float* __restrict__ w2, const float* __restrict__ b2)
{
    int row = blockIdx.x, tid = threadIdx.x;
    const float4* xr = (const float4*)(x + (size_t)row * CEMB);
    float4 a = xr[tid], b = xr[tid + 256];

    float s = a.x + a.y + a.z + a.w + b.x + b.y + b.z + b.w;
    float q = a.x*a.x + a.y*a.y + a.z*a.z + a.w*a.w
            + b.x*b.x + b.y*b.y + b.z*b.z + b.w*b.w;
    #pragma unroll
    for (int o = 16; o; o >>= 1) {
        s += __shfl_xor_sync(0xffffffffu, s, o);
        q += __shfl_xor_sync(0xffffffffu, q, o);
    }
    __shared__ float rs[8], rq[8], s_mu, s_rstd;
    int wid = tid >> 5, lane = tid & 31;
    if (!lane) { rs[wid] = s; rq[wid] = q; }
    __syncthreads();
    if (tid == 0) {
        float S = 0.f, Q = 0.f;
        #pragma unroll
        for (int i = 0; i < 8; i++) { S += rs[i]; Q += rq[i]; }
        float mu  = S * (1.0f / CEMB);
        float var = Q * (1.0f / CEMB) - mu * mu;
        s_mu = mu;
        s_rstd = rsqrtf(var + 1e-5f);
    }
    __syncthreads();
    float mu = s_mu, r = s_rstd;

    const float4* W1 = (const float4*)w1; const float4* B1 = (const float4*)b1;
    const float4* W2 = (const float4*)w2; const float4* B2 = (const float4*)b2;
    float4* o1 = (float4*)(g_xn1 + (size_t)row * CEMB);
    float4* o2 = (float4*)(g_xn2 + (size_t)row * CEMB);

    float4 w1a = W1[tid], w1b = W1[tid+256], b1a = B1[tid], b1b = B1[tid+256];
    float4 w2a = W2[tid], w2b = W2[tid+256], b2a = B2[tid], b2b = B2[tid+256];

    float4 na, nb;
    na.x = (a.x-mu)*r; na.y = (a.y-mu)*r; na.z = (a.z-mu)*r; na.w = (a.w-mu)*r;
    nb.x = (b.x-mu)*r; nb.y = (b.y-mu)*r; nb.z = (b.z-mu)*r; nb.w = (b.w-mu)*r;

    float4 t;
    t.x = to_tf32(na.x*w1a.x+b1a.x); t.y = to_tf32(na.y*w1a.y+b1a.y);
    t.z = to_tf32(na.z*w1a.z+b1a.z); t.w = to_tf32(na.w*w1a.w+b1a.w);
    o1[tid] = t;
    t.x = to_tf32(nb.x*w1b.x+b1b.x); t.y = to_tf32(nb.y*w1b.y+b1b.y);
    t.z = to_tf32(nb.z*w1b.z+b1b.z); t.w = to_tf32(nb.w*w1b.w+b1b.w);
    o1[tid+256] = t;
    t.x = to_tf32(na.x*w2a.x+b2a.x); t.y = to_tf32(na.y*w2a.y+b2a.y);
    t.z = to_tf32(na.z*w2a.z+b2a.z); t.w = to_tf32(na.w*w2a.w+b2a.w);
    o2[tid] = t;
    t.x = to_tf32(nb.x*w2b.x+b2b.x); t.y = to_tf32(nb.y*w2b.y+b2b.y);
    t.z = to_tf32(nb.z*w2b.z+b2b.z); t.w = to_tf32(nb.w*w2b.w+b2b.w);
    o2[tid+256] = t;
}

// ---------------- RoPE (in-place, tf32-rounded outputs) ----------------------
__global__ void __launch_bounds__(320) rope_kernel(
    const float* __restrict__ cosb, const float* __restrict__ sinb)
{
    int row = blockIdx.x;
    int t   = row & (TSEQ - 1);
    int tid = threadIdx.x;
    int head = tid >> 4;
    int i    = tid & 15;

    float* base;
    if (head < 16) {
        int g = head >> 2, slot = head & 3;
        base = g_qkv + (size_t)row * QKVN + g * 768 + slot * 128;
    } else {
        int g = head - 16;
        base = g_qkv + (size_t)row * QKVN + g * 768 + 512;
    }
    float c1 = cosb[t*32 + i],      s1 = sinb[t*32 + i];
    float c2 = cosb[t*32 + i + 16], s2 = sinb[t*32 + i + 16];
    float x1 = base[i], x2 = base[i + 16];
    base[i]      = to_tf32(x1 * c1 - x2 * s1);
    base[i + 16] = to_tf32(x2 * c2 + x1 * s2);
}

// ======================= R11-proven 128x128 tf32 GEMM ========================
enum { EPI_CVT = 0, EPI_RESID = 1, EPI_GELU = 2, EPI_ADDOUT = 3 };

#define ASTN 2048          // A floats per stage (128*16)
#define STG  4096          // A + B floats per stage = 16384 B
#define MM_SMEM (4 * STG * 4)   // 65536 B

__device__ __forceinline__ void stage_mma(
    const float* As, const float* Bs, int wm, int wn, int lr, int lc,
    float acc[4][4][4])
{
    float4 bv[4];
    #pragma unroll
    for (int ntt = 0; ntt < 4; ntt++)
        bv[ntt] = *(const float4*)&Bs[(wn + ntt*8 + lr)*16 + lc*4];
    #pragma unroll
    for (int mt = 0; mt < 4; mt++) {
        float4 alo = *(const float4*)&As[(wm + mt*16 + lr)*16 + lc*4];
        float4 ahi = *(const float4*)&As[(wm + mt*16 + 8 + lr)*16 + lc*4];
        uint32_t a0[4] = { __float_as_uint(alo.x), __float_as_uint(ahi.x),
                           __float_as_uint(alo.y), __float_as_uint(ahi.y) };
        uint32_t a1[4] = { __float_as_uint(alo.z), __float_as_uint(ahi.z),
                           __float_as_uint(alo.w), __float_as_uint(ahi.w) };
        #pragma unroll
        for (int ntt = 0; ntt < 4; ntt++) {
            uint32_t b0[2] = { __float_as_uint(bv[ntt].x), __float_as_uint(bv[ntt].y) };
            mma8(acc[mt][ntt], a0, b0);
        }
        #pragma unroll
        for (int ntt = 0; ntt < 4; ntt++) {
            uint32_t b1[2] = { __float_as_uint(bv[ntt].z), __float_as_uint(bv[ntt].w) };
            mma8(acc[mt][ntt], a1, b1);
        }
    }
}

template<int EPI>
__global__ void __launch_bounds__(256, 2) mm_pipe(
    const float* __restrict__ A,      // [M][K] row-major, tf32-rounded
    const float* __restrict__ Bt,     // [N][K] row-major (transposed weights)
    float* __restrict__ C, int ldc,
    const float* __restrict__ bias,
    const float* __restrict__ resid,
    int K)
{
    extern __shared__ float sm[];
    const int tid = threadIdx.x, lane = tid & 31, wid = tid >> 5;
    const int wm = (wid >> 2) * 64, wn = (wid & 3) * 32;
    const int lr = lane >> 2, lc = lane & 3;
    const int m0 = blockIdx.y * 128, n0 = blockIdx.x * 128;
    const uint32_t smb = (uint32_t)__cvta_generic_to_shared(sm);

    const int r0 = tid >> 2,        cq0 = (tid & 3) * 4;
    const int r1 = (tid + 256) >> 2;
    const float* Asrc0 = A  + (size_t)(m0 + r0) * K + cq0;
    const float* Asrc1 = A  + (size_t)(m0 + r1) * K + cq0;
    const float* Bsrc0 = Bt + (size_t)(n0 + r0) * K + cq0;
    const float* Bsrc1 = Bt + (size_t)(n0 + r1) * K + cq0;
    const uint32_t Ad0 = smb + (uint32_t)(r0*16 + cq0) * 4;
    const uint32_t Ad1 = smb + (uint32_t)(r1*16 + cq0) * 4;
    const uint32_t Bd0 = smb + (uint32_t)(ASTN + r0*16 + cq0) * 4;
    const uint32_t Bd1 = smb + (uint32_t)(ASTN + r1*16 + cq0) * 4;

    const int nt = K >> 4;
    auto issue = [&](int i) {
        uint32_t so = (uint32_t)(i & 3) * (STG * 4);
        int k0 = i << 4;
        cp16(Ad0 + so, Asrc0 + k0);
        cp16(Ad1 + so, Asrc1 + k0);
        cp16(Bd0 + so, Bsrc0 + k0);
        cp16(Bd1 + so, Bsrc1 + k0);
    };
    issue(0); cp_commit();
    issue(1); cp_commit();

    float acc[4][4][4];
    #pragma unroll
    for (int mt = 0; mt < 4; mt++)
        #pragma unroll
        for (int ntt = 0; ntt < 4; ntt++)
            #pragma unroll
            for (int i = 0; i < 4; i++) acc[mt][ntt][i] = 0.f;

    for (int i = 0; i < nt; i++) {
        if (i + 2 < nt) issue(i + 2);
        cp_commit();
        cp_wait2();
        __syncthreads();
        const float* As = sm + (size_t)(i & 3) * STG;
        stage_mma(As, As + ASTN, wm, wn, lr, lc, acc);
    }

    #pragma unroll
    for (int mt = 0; mt < 4; mt++) {
        int r = m0 + wm + mt*16 + lr;
        #pragma unroll
        for (int ntt = 0; ntt < 4; ntt++) {
            int cn = n0 + wn + ntt*8 + lc*2;
            float bx = bias[cn], by = bias[cn+1];
            float* p0 = C + (size_t)r * ldc + cn;
            float* p1 = C + (size_t)(r+8) * ldc + cn;
            float v0 = acc[mt][ntt][0] + bx, v1 = acc[mt][ntt][1] + by;
            float v2 = acc[mt][ntt][2] + bx, v3 = acc[mt][ntt][3] + by;
            if (EPI == EPI_RESID) {
                const float* q0 = resid + (size_t)r * ldc + cn;
                const float* q1 = resid + (size_t)(r+8) * ldc + cn;
                v0 += q0[0]; v1 += q0[1]; v2 += q1[0]; v3 += q1[1];
            }
            if (EPI == EPI_GELU) {
                v0 = to_tf32(0.5f*v0*(1.0f + erff(v0*0.70710678118654752f)));
                v1 = to_tf32(0.5f*v1*(1.0f + erff(v1*0.70710678118654752f)));
                v2 = to_tf32(0.5f*v2*(1.0f + erff(v2*0.70710678118654752f)));
                v3 = to_tf32(0.5f*v3*(1.0f + erff(v3*0.70710678118654752f)));
            }
            if (EPI == EPI_ADDOUT) { v0 += p0[0]; v1 += p0[1]; v2 += p1[0]; v3 += p1[1]; }
            if (EPI == EPI_CVT) { v0 = to_tf32(v0); v1 = to_tf32(v1); v2 = to_tf32(v2); v3 = to_tf32(v3); }
            p0[0] = v0; p0[1] = v1; p1[0] = v2; p1[1] = v3;
        }
    }
}

// ---------------- attention: P_unnorm = exp(QK^T*scale), fused partial sums --
// Exact triangular grid: blockIdx.x in [0,136) decodes to (ti, si), si <= ti.
__global__ void __launch_bounds__(256, 2) attn_scores_mma()
{
    int idx = blockIdx.x;
    int ti = (int)((__fsqrt_rn(8.f * (float)idx + 1.f) - 1.f) * 0.5f);
    while ((ti + 1) * (ti + 2) / 2 <= idx) ti++;
    while (ti * (ti + 1) / 2 > idx) ti--;
    int si = idx - ti * (ti + 1) / 2;

    int bh = blockIdx.z;
    int b = bh >> 4, h = bh & 15, g = h >> 2, sl = h & 3;

    const float* Q  = g_qkv + (size_t)b*TSEQ*QKVN + g*768 + sl*128 + (size_t)ti*128*QKVN;
    const float* Kp = g_qkv + (size_t)b*TSEQ*QKVN + g*768 + 512    + (size_t)si*128*QKVN;

    extern __shared__ float sm[];
    const int tid = threadIdx.x, lane = tid & 31, wid = tid >> 5;
    const int wm = (wid >> 2) * 64, wn = (wid & 3) * 32;
    const int lr = lane >> 2, lc = lane & 3;
    const uint32_t smb = (uint32_t)__cvta_generic_to_shared(sm);

    const int r0 = tid >> 2,        cq0 = (tid & 3) * 4;
    const int r1 = (tid + 256) >> 2;
    const float* Asrc0 = Q  + (size_t)r0 * QKVN + cq0;
    const float* Asrc1 = Q  + (size_t)r1 * QKVN + cq0;
    const float* Bsrc0 = Kp + (size_t)r0 * QKVN + cq0;
    const float* Bsrc1 = Kp + (size_t)r1 * QKVN + cq0;
    const uint32_t Ad0 = smb + (uint32_t)(r0*16 + cq0) * 4;
    const uint32_t Ad1 = smb + (uint32_t)(r1*16 + cq0) * 4;
    const uint32_t Bd0 = smb + (uint32_t)(ASTN + r0*16 + cq0) * 4;
    const uint32_t Bd1 = smb + (uint32_t)(ASTN + r1*16 + cq0) * 4;

    auto issue = [&](int i) {
        uint32_t so = (uint32_t)(i & 3) * (STG * 4);
        int k0 = i << 4;
        cp16(Ad0 + so, Asrc0 + k0);
        cp16(Ad1 + so, Asrc1 + k0);
        cp16(Bd0 + so, Bsrc0 + k0);
        cp16(Bd1 + so, Bsrc1 + k0);
    };
    issue(0); cp_commit();
    issue(1); cp_commit();

    float acc[4][4][4];
    #pragma unroll
    for (int mt = 0; mt < 4; mt++)
        #pragma unroll
        for (int ntt = 0; ntt < 4; ntt++)
            #pragma unroll
            for (int i = 0; i < 4; i++) acc[mt][ntt][i] = 0.f;

    for (int i = 0; i < 8; i++) {
        if (i + 2 < 8) issue(i + 2);
        cp_commit();
        cp_wait2();
        __syncthreads();
        const float* As = sm + (size_t)(i & 3) * STG;
        stage_mma(As, As + ASTN, wm, wn, lr, lc, acc);
    }

    // Epilogue: P = exp(S*scale) (masked->0), write + per-row partial sums.
    float* S = g_scores + (size_t)bh * TSEQ * TSEQ;
    float sum0[4], sum1[4];
    #pragma unroll
    for (int mt = 0; mt < 4; mt++) {
        int t0 = ti*128 + wm + mt*16 + lr;
        int t1 = t0 + 8;
        float a0 = 0.f, a1 = 0.f;
        #pragma unroll
        for (int ntt = 0; ntt < 4; ntt++) {
            int s0 = si*128 + wn + ntt*8 + lc*2;
            float e00 = (s0   <= t0) ? to_tf32(__expf(acc[mt][ntt][0]*SCALE)) : 0.f;
            float e01 = (s0+1 <= t0) ? to_tf32(__expf(acc[mt][ntt][1]*SCALE)) : 0.f;
            float e10 = (s0   <= t1) ? to_tf32(__expf(acc[mt][ntt][2]*SCALE)) : 0.f;
            float e11 = (s0+1 <= t1) ? to_tf32(__expf(acc[mt][ntt][3]*SCALE)) : 0.f;
            S[(size_t)t0*TSEQ + s0  ] = e00;
            S[(size_t)t0*TSEQ + s0+1] = e01;
            S[(size_t)t1*TSEQ + s0  ] = e10;
            S[(size_t)t1*TSEQ + s0+1] = e11;
            a0 += e00 + e01;
            a1 += e10 + e11;
        }
        sum0[mt] = a0; sum1[mt] = a1;
    }
    // reduce over lc (lane bits 0-1)
    #pragma unroll
    for (int mt = 0; mt < 4; mt++) {
        sum0[mt] += __shfl_xor_sync(0xffffffffu, sum0[mt], 1);
        sum0[mt] += __shfl_xor_sync(0xffffffffu, sum0[mt], 2);
        sum1[mt] += __shfl_xor_sync(0xffffffffu, sum1[mt], 1);
        sum1[mt] += __shfl_xor_sync(0xffffffffu, sum1[mt], 2);
    }
    __syncthreads();                 // all warps done reading stage smem
    float* ps = sm;                  // reuse ring smem: [128 rows][4 n-warps]
    if (lc == 0) {
        int wq = wid & 3;
        #pragma unroll
        for (int mt = 0; mt < 4; mt++) {
            ps[(wm + mt*16 + lr)*4 + wq]     = sum0[mt];
            ps[(wm + mt*16 + 8 + lr)*4 + wq] = sum1[mt];
        }
    }
    __syncthreads();
    if (tid < 128) {
        float tot = ps[tid*4] + ps[tid*4+1] + ps[tid*4+2] + ps[tid*4+3];
        g_psum[((size_t)bh*TSEQ + ti*128 + tid)*16 + si] = tot;
    }
}

// ---------------- attention: Y = (P V) / rowsum (heavy tiles first) ----------
__global__ void __launch_bounds__(256, 2) attn_av_mma()
{
    int ti = 15 - (int)blockIdx.x;    // heavy tiles dispatched first
    int bh = blockIdx.y;
    int b = bh >> 4, h = bh & 15, g = h >> 2;

    const float* P  = g_scores + (size_t)bh * TSEQ * TSEQ + (size_t)ti*128 * TSEQ;
    const float* Vt = g_vt + (size_t)(b*NGRP + g) * HD * TSEQ;

    extern __shared__ float sm[];
    __shared__ float s_inv[128];
    const int tid = threadIdx.x, lane = tid & 31, wid = tid >> 5;
    const int wm = (wid >> 2) * 64, wn = (wid & 3) * 32;
    const int lr = lane >> 2, lc = lane & 3;
    const uint32_t smb = (uint32_t)__cvta_generic_to_shared(sm);

    // row normalizers from per-tile partial sums
    if (tid < 128) {
        const float* pp = g_psum + ((size_t)bh*TSEQ + ti*128 + tid)*16;
        float s = 0.f;
        for (int c = 0; c <= ti; c++) s += pp[c];
        s_inv[tid] = 1.0f / s;
    }

    const int r0 = tid >> 2,        cq0 = (tid & 3) * 4;
    const int r1 = (tid + 256) >> 2;
    const float* Asrc0 = P  + (size_t)r0 * TSEQ + cq0;
    const float* Asrc1 = P  + (size_t)r1 * TSEQ + cq0;
    const float* Bsrc0 = Vt + (size_t)r0 * TSEQ + cq0;
    const float* Bsrc1 = Vt + (size_t)r1 * TSEQ + cq0;
    const uint32_t Ad0 = smb + (uint32_t)(r0*16 + cq0) * 4;
    const uint32_t Ad1 = smb + (uint32_t)(r1*16 + cq0) * 4;
    const uint32_t Bd0 = smb + (uint32_t)(ASTN + r0*16 + cq0) * 4;
    const uint32_t Bd1 = smb + (uint32_t)(ASTN + r1*16 + cq0) * 4;

    const int nt = (ti + 1) * 8;
    auto issue = [&](int i) {
        uint32_t so = (uint32_t)(i & 3) * (STG * 4);
        int k0 = i << 4;
        cp16(Ad0 + so, Asrc0 + k0);
        cp16(Ad1 + so, Asrc1 + k0);
        cp16(Bd0 + so, Bsrc0 + k0);
        cp16(Bd1 + so, Bsrc1 + k0);
    };
    issue(0); cp_commit();
    issue(1); cp_commit();

    float acc[4][4][4];
    #pragma unroll
    for (int mt = 0; mt < 4; mt++)
        #pragma unroll
        for (int ntt = 0; ntt < 4; ntt++)
            #pragma unroll
            for (int i = 0; i < 4; i++) acc[mt][ntt][i] = 0.f;

    for (int i = 0; i < nt; i++) {
        if (i + 2 < nt) issue(i + 2);
        cp_commit();
        cp_wait2();
        __syncthreads();                 // also orders s_inv writes vs epilogue reads
        const float* As = sm + (size_t)(i & 3) * STG;
        stage_mma(As, As + ASTN, wm, wn, lr, lc, acc);
    }

    float* Y = g_y + (size_t)(b*TSEQ + ti*128) * CEMB + h*128;
    #pragma unroll
    for (int mt = 0; mt < 4; mt++) {
        int rr = wm + mt*16 + lr;
        float inv0 = s_inv[rr], inv1 = s_inv[rr + 8];
        #pragma unroll
        for (int ntt = 0; ntt < 4; ntt++) {
            int dd = wn + ntt*8 + lc*2;
            Y[(size_t)rr*CEMB + dd  ]     = to_tf32(acc[mt][ntt][0] * inv0);
            Y[(size_t)rr*CEMB + dd+1]     = to_tf32(acc[mt][ntt][1] * inv0);
            Y[(size_t)(rr+8)*CEMB + dd  ] = to_tf32(acc[mt][ntt][2] * inv1);
            Y[(size_t)(rr+8)*CEMB + dd+1] = to_tf32(acc[mt][ntt][3] * inv1);
        }
    }
}

// ---------------- launch ----------------------------------------------------
extern "C" void kernel_launch(void* const* d_in, const int* in_sizes, int n_in,
                              void* d_out, int out_size)
{
    (void)in_sizes; (void)n_in; (void)out_size;
    const float* x     = (const float*)d_in[0];
    const float* cosb  = (const float*)d_in[1];
    const float* sinb  = (const float*)d_in[2];
    const float* ln1w  = (const float*)d_in[3];
    const float* ln1b  = (const float*)d_in[4];
    const float* wqkv  = (const float*)d_in[5];
    const float* bqkv  = (const float*)d_in[6];
    const float* wproj = (const float*)d_in[7];
    const float* bproj = (const float*)d_in[8];
    const float* ln2w  = (const float*)d_in[9];
    const float* ln2b  = (const float*)d_in[10];
    const float* wfc1  = (const float*)d_in[11];
    const float* bfc1  = (const float*)d_in[12];
    const float* wfc2  = (const float*)d_in[13];
    const float* bfc2  = (const float*)d_in[14];
    float* out = (float*)d_out;

    float *xn1, *xn2, *qkv, *yv, *act, *wc;
    cudaGetSymbolAddress((void**)&xn1, g_xn1);
    cudaGetSymbolAddress((void**)&xn2, g_xn2);
    cudaGetSymbolAddress((void**)&qkv, g_qkv);
    cudaGetSymbolAddress((void**)&yv,  g_y);
    cudaGetSymbolAddress((void**)&act, g_act);
    cudaGetSymbolAddress((void**)&wc,  g_wcvt);
    float* wqkv_t  = wc;                 // [3072][2048]
    float* wproj_t = wc + 6291456;       // [2048][2048]
    float* wfc1_t  = wc + 10485760;      // [8192][2048]
    float* wfc2_t  = wc + 27262976;      // [2048][8192]

    cudaFuncSetAttribute(mm_pipe<EPI_CVT>,    cudaFuncAttributeMaxDynamicSharedMemorySize, MM_SMEM);
    cudaFuncSetAttribute(mm_pipe<EPI_RESID>,  cudaFuncAttributeMaxDynamicSharedMemorySize, MM_SMEM);
    cudaFuncSetAttribute(mm_pipe<EPI_GELU>,   cudaFuncAttributeMaxDynamicSharedMemorySize, MM_SMEM);
    cudaFuncSetAttribute(mm_pipe<EPI_ADDOUT>, cudaFuncAttributeMaxDynamicSharedMemorySize, MM_SMEM);
    cudaFuncSetAttribute(attn_scores_mma,     cudaFuncAttributeMaxDynamicSharedMemorySize, MM_SMEM);
    cudaFuncSetAttribute(attn_av_mma,         cudaFuncAttributeMaxDynamicSharedMemorySize, MM_SMEM);

    // 0. tf32-round + transpose all weights to [N][K]
    wtrans_kernel<<<dim3(QKVN/32, CEMB/32), 256>>>(wqkv,  wqkv_t,  CEMB, QKVN);
    wtrans_kernel<<<dim3(CEMB/32, CEMB/32), 256>>>(wproj, wproj_t, CEMB, CEMB);
    wtrans_kernel<<<dim3(FFN/32,  CEMB/32), 256>>>(wfc1,  wfc1_t,  CEMB, FFN);
    wtrans_kernel<<<dim3(CEMB/32, FFN/32),  256>>>(wfc2,  wfc2_t,  FFN,  CEMB);

    // 1. LN1 + LN2 (shared statistics, tf32-rounded outputs)
    ln_kernel<<<MROWS, 256>>>(x, ln1w, ln1b, ln2w, ln2b);

    // 2. QKV GEMM (tf32-rounded output)
    mm_pipe<EPI_CVT><<<dim3(QKVN/128, MROWS/128), 256, MM_SMEM>>>(
        xn1, wqkv_t, qkv, QKVN, bqkv, nullptr, CEMB);

    // 3. RoPE in-place, V transpose
    rope_kernel<<<MROWS, 320>>>(cosb, sinb);
    vtrans_kernel<<<dim3(TSEQ/32, HD/32, BATCH*NGRP), 256>>>();

    // 4. P_unnorm + partial row sums (exact triangle), 5. normalized P·V
    attn_scores_mma<<<dim3(136, 1, BATCH*NHEAD), 256, MM_SMEM>>>();
    attn_av_mma<<<dim3(16, BATCH*NHEAD), 256, MM_SMEM>>>();

    // 6. proj GEMM (+b_proj + x residual) -> d_out
    mm_pipe<EPI_RESID><<<dim3(CEMB/128, MROWS/128), 256, MM_SMEM>>>(
        yv, wproj_t, out, CEMB, bproj, x, CEMB);

    // 7. fc1 GEMM + exact GELU (tf32-rounded)
    mm_pipe<EPI_GELU><<<dim3(FFN/128, MROWS/128), 256, MM_SMEM>>>(
        xn2, wfc1_t, act, FFN, bfc1, nullptr, CEMB);

    // 8. fc2 GEMM adds into d_out
    mm_pipe<EPI_ADDOUT><<<dim3(CEMB/128, MROWS/128), 256, MM_SMEM>>>(
        act, wfc2_t, out, CEMB, bfc2, nullptr, FFN);
}

// round 16
// speedup vs baseline: 1.1399x; 1.0233x over previous
#include <cuda_runtime.h>
#include <math.h>
#include <stdint.h>

#define TSEQ 2048
#define CEMB 2048
#define BATCH 2
#define NHEAD 16
#define NGRP 4
#define HD 128
#define QKVN 3072          // (16 + 2*4) * 128
#define FFN 8192
#define MROWS 4096         // B*T
#define SCALE 0.08838834764831845f  // 1/sqrt(128)

// ---------------- scratch (device globals: allocation-free rule) -------------
__device__ float g_xn1[MROWS * CEMB];
__device__ float g_xn2[MROWS * CEMB];
__device__ float g_qkv[MROWS * QKVN];
__device__ float g_y  [MROWS * CEMB];
__device__ float g_act[(size_t)MROWS * FFN];
__device__ float g_scores[(size_t)BATCH * NHEAD * TSEQ * TSEQ];  // holds P_unnorm
__device__ float g_psum[(size_t)BATCH * NHEAD * TSEQ * 16];      // per-tile row sums
__device__ float g_wcvt[44040192];   // tf32-rounded TRANSPOSED weights
__device__ float g_vt[(size_t)BATCH * NGRP * HD * TSEQ];  // V transposed [b*g][d][s]

// ---------------- tf32 / mma / cp.async helpers ------------------------------
__device__ __forceinline__ float to_tf32(float x) {
    asm("cvt.rna.tf32.f32 %0, %0;" : "+f"(x));
    return x;
}

__device__ __forceinline__ void mma8(float c[4], const uint32_t a[4], const uint32_t b[2]) {
    asm volatile(
        "mma.sync.aligned.m16n8k8.row.col.f32.tf32.tf32.f32 "
        "{%0,%1,%2,%3}, {%4,%5,%6,%7}, {%8,%9}, {%0,%1,%2,%3};\n"
        : "+f"(c[0]), "+f"(c[1]), "+f"(c[2]), "+f"(c[3])
        : "r"(a[0]), "r"(a[1]), "r"(a[2]), "r"(a[3]), "r"(b[0]), "r"(b[1]));
}

__device__ __forceinline__ void cp16(uint32_t dst, const void* src) {
    asm volatile("cp.async.cg.shared.global [%0], [%1], 16;" :: "r"(dst), "l"(src));
}
__device__ __forceinline__ void cp_commit() { asm volatile("cp.async.commit_group;"); }
__device__ __forceinline__ void cp_wait2()  { asm volatile("cp.async.wait_group 2;"); }

// ---------------- weight tf32 round + transpose [K][N] -> [N][K] -------------
__global__ void __launch_bounds__(256) wtrans_kernel(
    const float* __restrict__ in, float* __restrict__ outp, int K, int N)
{
    __shared__ float t[32][33];
    int nb = blockIdx.x * 32, kb = blockIdx.y * 32;
    int tx = threadIdx.x & 31, ty = threadIdx.x >> 5;
    #pragma unroll
    for (int i = 0; i < 4; i++)
        t[ty + i*8][tx] = in[(size_t)(kb + ty + i*8) * N + nb + tx];
    __syncthreads();
    #pragma unroll
    for (int i = 0; i < 4; i++)
        outp[(size_t)(nb + ty + i*8) * K + kb + tx] = to_tf32(t[tx][ty + i*8]);
}

// ---------------- V transpose: g_qkv v-slices -> g_vt[bg][d][s] --------------
__global__ void __launch_bounds__(256) vtrans_kernel()
{
    __shared__ float t[32][33];
    int z = blockIdx.z;
    int b = z >> 2, g = z & 3;
    int sb = blockIdx.x * 32, db = blockIdx.y * 32;
    int tx = threadIdx.x & 31, ty = threadIdx.x >> 5;
    #pragma unroll
    for (int i = 0; i < 4; i++)
        t[ty + i*8][tx] = g_qkv[(size_t)(b*TSEQ + sb + ty + i*8) * QKVN + g*768 + 640 + db + tx];
    __syncthreads();
    #pragma unroll
    for (int i = 0; i < 4; i++)
        g_vt[((size_t)z * HD + db + ty + i*8) * TSEQ + sb + tx] = t[tx][ty + i*8];
}

// ---------------- fused double LayerNorm (tf32-rounded outputs) --------------
__global__ void __launch_bounds__(256) ln_kernel(
    const float* __restrict__ x,
    const float* __restrict__ w1, const float* __restrict__ b1,
    const float* __restrict__ w2, const float* __restrict__ b2)
{
    int row = blockIdx.x, tid = threadIdx.x;
    const float4* xr = (const float4*)(x + (size_t)row * CEMB);
    float4 a = xr[tid], b = xr[tid + 256];

    float s = a.x + a.y + a.z + a.w + b.x + b.y + b.z + b.w;
    float q = a.x*a.x + a.y*a.y + a.z*a.z + a.w*a.w
            + b.x*b.x + b.y*b.y + b.z*b.z + b.w*b.w;
    #pragma unroll
    for (int o = 16; o; o >>= 1) {
        s += __shfl_xor_sync(0xffffffffu, s, o);
        q += __shfl_xor_sync(0xffffffffu, q, o);
    }
    __shared__ float rs[8], rq[8], s_mu, s_rstd;
    int wid = tid >> 5, lane = tid & 31;
    if (!lane) { rs[wid] = s; rq[wid] = q; }
    __syncthreads();
    if (tid == 0) {
        float S = 0.f, Q = 0.f;
        #pragma unroll
        for (int i = 0; i < 8; i++) { S += rs[i]; Q += rq[i]; }
        float mu  = S * (1.0f / CEMB);
        float var = Q * (1.0f / CEMB) - mu * mu;
        s_mu = mu;
        s_rstd = rsqrtf(var + 1e-5f);
    }
    __syncthreads();
    float mu = s_mu, r = s_rstd;

    const float4* W1 = (const float4*)w1; const float4* B1 = (const float4*)b1;
    const float4* W2 = (const float4*)w2; const float4* B2 = (const float4*)b2;
    float4* o1 = (float4*)(g_xn1 + (size_t)row * CEMB);
    float4* o2 = (float4*)(g_xn2 + (size_t)row * CEMB);

    float4 w1a = W1[tid], w1b = W1[tid+256], b1a = B1[tid], b1b = B1[tid+256];
    float4 w2a = W2[tid], w2b = W2[tid+256], b2a = B2[tid], b2b = B2[tid+256];

    float4 na, nb;
    na.x = (a.x-mu)*r; na.y = (a.y-mu)*r; na.z = (a.z-mu)*r; na.w = (a.w-mu)*r;
    nb.x = (b.x-mu)*r; nb.y = (b.y-mu)*r; nb.z = (b.z-mu)*r; nb.w = (b.w-mu)*r;

    float4 t;
    t.x = to_tf32(na.x*w1a.x+b1a.x); t.y = to_tf32(na.y*w1a.y+b1a.y);
    t.z = to_tf32(na.z*w1a.z+b1a.z); t.w = to_tf32(na.w*w1a.w+b1a.w);
    o1[tid] = t;
    t.x = to_tf32(nb.x*w1b.x+b1b.x); t.y = to_tf32(nb.y*w1b.y+b1b.y);
    t.z = to_tf32(nb.z*w1b.z+b1b.z); t.w = to_tf32(nb.w*w1b.w+b1b.w);
    o1[tid+256] = t;
    t.x = to_tf32(na.x*w2a.x+b2a.x); t.y = to_tf32(na.y*w2a.y+b2a.y);
    t.z = to_tf32(na.z*w2a.z+b2a.z); t.w = to_tf32(na.w*w2a.w+b2a.w);
    o2[tid] = t;
    t.x = to_tf32(nb.x*w2b.x+b2b.x); t.y = to_tf32(nb.y*w2b.y+b2b.y);
    t.z = to_tf32(nb.z*w2b.z+b2b.z); t.w = to_tf32(nb.w*w2b.w+b2b.w);
    o2[tid+256] = t;
}

// ---------------- RoPE (in-place, tf32-rounded outputs) ----------------------
__global__ void __launch_bounds__(320) rope_kernel(
    const float* __restrict__ cosb, const float* __restrict__ sinb)
{
    int row = blockIdx.x;
    int t   = row & (TSEQ - 1);
    int tid = threadIdx.x;
    int head = tid >> 4;
    int i    = tid & 15;

    float* base;
    if (head < 16) {
        int g = head >> 2, slot = head & 3;
        base = g_qkv + (size_t)row * QKVN + g * 768 + slot * 128;
    } else {
        int g = head - 16;
        base = g_qkv + (size_t)row * QKVN + g * 768 + 512;
    }
    float c1 = cosb[t*32 + i],      s1 = sinb[t*32 + i];
    float c2 = cosb[t*32 + i + 16], s2 = sinb[t*32 + i + 16];
    float x1 = base[i], x2 = base[i + 16];
    base[i]      = to_tf32(x1 * c1 - x2 * s1);
    base[i + 16] = to_tf32(x2 * c2 + x1 * s2);
}

// ======================= R11-proven 128x128 tf32 GEMM ========================
enum { EPI_CVT = 0, EPI_RESID = 1, EPI_GELU = 2, EPI_ADDOUT = 3 };

#define ASTN 2048          // A floats per stage (128*16)
#define STG  4096          // A + B floats per stage = 16384 B
#define MM_SMEM (4 * STG * 4)   // 65536 B

__device__ __forceinline__ void stage_mma(
    const float* As, const float* Bs, int wm, int wn, int lr, int lc,
    float acc[4][4][4])
{
    float4 bv[4];
    #pragma unroll
    for (int ntt = 0; ntt < 4; ntt++)
        bv[ntt] = *(const float4*)&Bs[(wn + ntt*8 + lr)*16 + lc*4];
    #pragma unroll
    for (int mt = 0; mt < 4; mt++) {
        float4 alo = *(const float4*)&As[(wm + mt*16 + lr)*16 + lc*4];
        float4 ahi = *(const float4*)&As[(wm + mt*16 + 8 + lr)*16 + lc*4];
        uint32_t a0[4] = { __float_as_uint(alo.x), __float_as_uint(ahi.x),
                           __float_as_uint(alo.y), __float_as_uint(ahi.y) };
        uint32_t a1[4] = { __float_as_uint(alo.z), __float_as_uint(ahi.z),
                           __float_as_uint(alo.w), __float_as_uint(ahi.w) };
        #pragma unroll
        for (int ntt = 0; ntt < 4; ntt++) {
            uint32_t b0[2] = { __float_as_uint(bv[ntt].x), __float_as_uint(bv[ntt].y) };
            mma8(acc[mt][ntt], a0, b0);
        }
        #pragma unroll
        for (int ntt = 0; ntt < 4; ntt++) {
            uint32_t b1[2] = { __float_as_uint(bv[ntt].z), __float_as_uint(bv[ntt].w) };
            mma8(acc[mt][ntt], a1, b1);
        }
    }
}

template<int EPI>
__global__ void __launch_bounds__(256, 2) mm_pipe(
    const float* __restrict__ A,      // [M][K] row-major, tf32-rounded
    const float* __restrict__ Bt,     // [N][K] row-major (transposed weights)
    float* __restrict__ C, int ldc,
    const float* __restrict__ bias,
    const float* __restrict__ resid,
    int K)
{
    extern __shared__ float sm[];
    const int tid = threadIdx.x, lane = tid & 31, wid = tid >> 5;
    const int wm = (wid >> 2) * 64, wn = (wid & 3) * 32;
    const int lr = lane >> 2, lc = lane & 3;
    const int m0 = blockIdx.y * 128, n0 = blockIdx.x * 128;
    const uint32_t smb = (uint32_t)__cvta_generic_to_shared(sm);

    const int r0 = tid >> 2,        cq0 = (tid & 3) * 4;
    const int r1 = (tid + 256) >> 2;
    const float* Asrc0 = A  + (size_t)(m0 + r0) * K + cq0;
    const float* Asrc1 = A  + (size_t)(m0 + r1) * K + cq0;
    const float* Bsrc0 = Bt + (size_t)(n0 + r0) * K + cq0;
    const float* Bsrc1 = Bt + (size_t)(n0 + r1) * K + cq0;
    const uint32_t Ad0 = smb + (uint32_t)(r0*16 + cq0) * 4;
    const uint32_t Ad1 = smb + (uint32_t)(r1*16 + cq0) * 4;
    const uint32_t Bd0 = smb + (uint32_t)(ASTN + r0*16 + cq0) * 4;
    const uint32_t Bd1 = smb + (uint32_t)(ASTN + r1*16 + cq0) * 4;

    const int nt = K >> 4;
    auto issue = [&](int i) {
        uint32_t so = (uint32_t)(i & 3) * (STG * 4);
        int k0 = i << 4;
        cp16(Ad0 + so, Asrc0 + k0);
        cp16(Ad1 + so, Asrc1 + k0);
        cp16(Bd0 + so, Bsrc0 + k0);
        cp16(Bd1 + so, Bsrc1 + k0);
    };
    issue(0); cp_commit();
    issue(1); cp_commit();

    float acc[4][4][4];
    #pragma unroll
    for (int mt = 0; mt < 4; mt++)
        #pragma unroll
        for (int ntt = 0; ntt < 4; ntt++)
            #pragma unroll
            for (int i = 0; i < 4; i++) acc[mt][ntt][i] = 0.f;

    for (int i = 0; i < nt; i++) {
        if (i + 2 < nt) issue(i + 2);
        cp_commit();
        cp_wait2();
        __syncthreads();
        const float* As = sm + (size_t)(i & 3) * STG;
        stage_mma(As, As + ASTN, wm, wn, lr, lc, acc);
    }

    #pragma unroll
    for (int mt = 0; mt < 4; mt++) {
        int r = m0 + wm + mt*16 + lr;
        #pragma unroll
        for (int ntt = 0; ntt < 4; ntt++) {
            int cn = n0 + wn + ntt*8 + lc*2;
            float bx = bias[cn], by = bias[cn+1];
            float* p0 = C + (size_t)r * ldc + cn;
            float* p1 = C + (size_t)(r+8) * ldc + cn;
            float v0 = acc[mt][ntt][0] + bx, v1 = acc[mt][ntt][1] + by;
            float v2 = acc[mt][ntt][2] + bx, v3 = acc[mt][ntt][3] + by;
            if (EPI == EPI_RESID) {
                const float* q0 = resid + (size_t)r * ldc + cn;
                const float* q1 = resid + (size_t)(r+8) * ldc + cn;
                v0 += q0[0]; v1 += q0[1]; v2 += q1[0]; v3 += q1[1];
            }
            if (EPI == EPI_GELU) {
                v0 = to_tf32(0.5f*v0*(1.0f + erff(v0*0.70710678118654752f)));
                v1 = to_tf32(0.5f*v1*(1.0f + erff(v1*0.70710678118654752f)));
                v2 = to_tf32(0.5f*v2*(1.0f + erff(v2*0.70710678118654752f)));
                v3 = to_tf32(0.5f*v3*(1.0f + erff(v3*0.70710678118654752f)));
            }
            if (EPI == EPI_ADDOUT) { v0 += p0[0]; v1 += p0[1]; v2 += p1[0]; v3 += p1[1]; }
            if (EPI == EPI_CVT) { v0 = to_tf32(v0); v1 = to_tf32(v1); v2 = to_tf32(v2); v3 = to_tf32(v3); }
            p0[0] = v0; p0[1] = v1; p1[0] = v2; p1[1] = v3;
        }
    }
}

// ---------------- attention: P_unnorm = exp(QK^T*scale), fused partial sums --
__global__ void __launch_bounds__(256, 2) attn_scores_mma()
{
    int idx = blockIdx.x;
    int ti = (int)((__fsqrt_rn(8.f * (float)idx + 1.f) - 1.f) * 0.5f);
    while ((ti + 1) * (ti + 2) / 2 <= idx) ti++;
    while (ti * (ti + 1) / 2 > idx) ti--;
    int si = idx - ti * (ti + 1) / 2;

    int bh = blockIdx.z;
    int b = bh >> 4, h = bh & 15, g = h >> 2, sl = h & 3;

    const float* Q  = g_qkv + (size_t)b*TSEQ*QKVN + g*768 + sl*128 + (size_t)ti*128*QKVN;
    const float* Kp = g_qkv + (size_t)b*TSEQ*QKVN + g*768 + 512    + (size_t)si*128*QKVN;

    extern __shared__ float sm[];
    const int tid = threadIdx.x, lane = tid & 31, wid = tid >> 5;
    const int wm = (wid >> 2) * 64, wn = (wid & 3) * 32;
    const int lr = lane >> 2, lc = lane & 3;
    const uint32_t smb = (uint32_t)__cvta_generic_to_shared(sm);

    const int r0 = tid >> 2,        cq0 = (tid & 3) * 4;
    const int r1 = (tid + 256) >> 2;
    const float* Asrc0 = Q  + (size_t)r0 * QKVN + cq0;
    const float* Asrc1 = Q  + (size_t)r1 * QKVN + cq0;
    const float* Bsrc0 = Kp + (size_t)r0 * QKVN + cq0;
    const float* Bsrc1 = Kp + (size_t)r1 * QKVN + cq0;
    const uint32_t Ad0 = smb + (uint32_t)(r0*16 + cq0) * 4;
    const uint32_t Ad1 = smb + (uint32_t)(r1*16 + cq0) * 4;
    const uint32_t Bd0 = smb + (uint32_t)(ASTN + r0*16 + cq0) * 4;
    const uint32_t Bd1 = smb + (uint32_t)(ASTN + r1*16 + cq0) * 4;

    auto issue = [&](int i) {
        uint32_t so = (uint32_t)(i & 3) * (STG * 4);
        int k0 = i << 4;
        cp16(Ad0 + so, Asrc0 + k0);
        cp16(Ad1 + so, Asrc1 + k0);
        cp16(Bd0 + so, Bsrc0 + k0);
        cp16(Bd1 + so, Bsrc1 + k0);
    };
    issue(0); cp_commit();
    issue(1); cp_commit();

    float acc[4][4][4];
    #pragma unroll
    for (int mt = 0; mt < 4; mt++)
        #pragma unroll
        for (int ntt = 0; ntt < 4; ntt++)
            #pragma unroll
            for (int i = 0; i < 4; i++) acc[mt][ntt][i] = 0.f;

    for (int i = 0; i < 8; i++) {
        if (i + 2 < 8) issue(i + 2);
        cp_commit();
        cp_wait2();
        __syncthreads();
        const float* As = sm + (size_t)(i & 3) * STG;
        stage_mma(As, As + ASTN, wm, wn, lr, lc, acc);
    }

    float* S = g_scores + (size_t)bh * TSEQ * TSEQ;
    float sum0[4], sum1[4];
    #pragma unroll
    for (int mt = 0; mt < 4; mt++) {
        int t0 = ti*128 + wm + mt*16 + lr;
        int t1 = t0 + 8;
        float a0 = 0.f, a1 = 0.f;
        #pragma unroll
        for (int ntt = 0; ntt < 4; ntt++) {
            int s0 = si*128 + wn + ntt*8 + lc*2;
            float e00 = (s0   <= t0) ? to_tf32(__expf(acc[mt][ntt][0]*SCALE)) : 0.f;
            float e01 = (s0+1 <= t0) ? to_tf32(__expf(acc[mt][ntt][1]*SCALE)) : 0.f;
            float e10 = (s0   <= t1) ? to_tf32(__expf(acc[mt][ntt][2]*SCALE)) : 0.f;
            float e11 = (s0+1 <= t1) ? to_tf32(__expf(acc[mt][ntt][3]*SCALE)) : 0.f;
            S[(size_t)t0*TSEQ + s0  ] = e00;
            S[(size_t)t0*TSEQ + s0+1] = e01;
            S[(size_t)t1*TSEQ + s0  ] = e10;
            S[(size_t)t1*TSEQ + s0+1] = e11;
            a0 += e00 + e01;
            a1 += e10 + e11;
        }
        sum0[mt] = a0; sum1[mt] = a1;
    }
    #pragma unroll
    for (int mt = 0; mt < 4; mt++) {
        sum0[mt] += __shfl_xor_sync(0xffffffffu, sum0[mt], 1);
        sum0[mt] += __shfl_xor_sync(0xffffffffu, sum0[mt], 2);
        sum1[mt] += __shfl_xor_sync(0xffffffffu, sum1[mt], 1);
        sum1[mt] += __shfl_xor_sync(0xffffffffu, sum1[mt], 2);
    }
    __syncthreads();
    float* ps = sm;
    if (lc == 0) {
        int wq = wid & 3;
        #pragma unroll
        for (int mt = 0; mt < 4; mt++) {
            ps[(wm + mt*16 + lr)*4 + wq]     = sum0[mt];
            ps[(wm + mt*16 + 8 + lr)*4 + wq] = sum1[mt];
        }
    }
    __syncthreads();
    if (tid < 128) {
        float tot = ps[tid*4] + ps[tid*4+1] + ps[tid*4+2] + ps[tid*4+3];
        g_psum[((size_t)bh*TSEQ + ti*128 + tid)*16 + si] = tot;
    }
}

// ---------------- attention: Y = (P V) / rowsum (heavy tiles first) ----------
__global__ void __launch_bounds__(256, 2) attn_av_mma()
{
    int ti = 15 - (int)blockIdx.x;
    int bh = blockIdx.y;
    int b = bh >> 4, h = bh & 15, g = h >> 2;

    const float* P  = g_scores + (size_t)bh * TSEQ * TSEQ + (size_t)ti*128 * TSEQ;
    const float* Vt = g_vt + (size_t)(b*NGRP + g) * HD * TSEQ;

    extern __shared__ float sm[];
    __shared__ float s_inv[128];
    const int tid = threadIdx.x, lane = tid & 31, wid = tid >> 5;
    const int wm = (wid >> 2) * 64, wn = (wid & 3) * 32;
    const int lr = lane >> 2, lc = lane & 3;
    const uint32_t smb = (uint32_t)__cvta_generic_to_shared(sm);

    if (tid < 128) {
        const float* pp = g_psum + ((size_t)bh*TSEQ + ti*128 + tid)*16;
        float s = 0.f;
        for (int c = 0; c <= ti; c++) s += pp[c];
        s_inv[tid] = 1.0f / s;
    }

    const int r0 = tid >> 2,        cq0 = (tid & 3) * 4;
    const int r1 = (tid + 256) >> 2;
    const float* Asrc0 = P  + (size_t)r0 * TSEQ + cq0;
    const float* Asrc1 = P  + (size_t)r1 * TSEQ + cq0;
    const float* Bsrc0 = Vt + (size_t)r0 * TSEQ + cq0;
    const float* Bsrc1 = Vt + (size_t)r1 * TSEQ + cq0;
    const uint32_t Ad0 = smb + (uint32_t)(r0*16 + cq0) * 4;
    const uint32_t Ad1 = smb + (uint32_t)(r1*16 + cq0) * 4;
    const uint32_t Bd0 = smb + (uint32_t)(ASTN + r0*16 + cq0) * 4;
    const uint32_t Bd1 = smb + (uint32_t)(ASTN + r1*16 + cq0) * 4;

    const int nt = (ti + 1) * 8;
    auto issue = [&](int i) {
        uint32_t so = (uint32_t)(i & 3) * (STG * 4);
        int k0 = i << 4;
        cp16(Ad0 + so, Asrc0 + k0);
        cp16(Ad1 + so, Asrc1 + k0);
        cp16(Bd0 + so, Bsrc0 + k0);
        cp16(Bd1 + so, Bsrc1 + k0);
    };
    issue(0); cp_commit();
    issue(1); cp_commit();

    float acc[4][4][4];
    #pragma unroll
    for (int mt = 0; mt < 4; mt++)
        #pragma unroll
        for (int ntt = 0; ntt < 4; ntt++)
            #pragma unroll
            for (int i = 0; i < 4; i++) acc[mt][ntt][i] = 0.f;

    for (int i = 0; i < nt; i++) {
        if (i + 2 < nt) issue(i + 2);
        cp_commit();
        cp_wait2();
        __syncthreads();
        const float* As = sm + (size_t)(i & 3) * STG;
        stage_mma(As, As + ASTN, wm, wn, lr, lc, acc);
    }

    float* Y = g_y + (size_t)(b*TSEQ + ti*128) * CEMB + h*128;
    #pragma unroll
    for (int mt = 0; mt < 4; mt++) {
        int rr = wm + mt*16 + lr;
        float inv0 = s_inv[rr], inv1 = s_inv[rr + 8];
        #pragma unroll
        for (int ntt = 0; ntt < 4; ntt++) {
            int dd = wn + ntt*8 + lc*2;
            Y[(size_t)rr*CEMB + dd  ]     = to_tf32(acc[mt][ntt][0] * inv0);
            Y[(size_t)rr*CEMB + dd+1]     = to_tf32(acc[mt][ntt][1] * inv0);
            Y[(size_t)(rr+8)*CEMB + dd  ] = to_tf32(acc[mt][ntt][2] * inv1);
            Y[(size_t)(rr+8)*CEMB + dd+1] = to_tf32(acc[mt][ntt][3] * inv1);
        }
    }
}

// ---------------- launch (multi-stream fork/join inside graph capture) -------
extern "C" void kernel_launch(void* const* d_in, const int* in_sizes, int n_in,
                              void* d_out, int out_size)
{
    (void)in_sizes; (void)n_in; (void)out_size;
    const float* x     = (const float*)d_in[0];
    const float* cosb  = (const float*)d_in[1];
    const float* sinb  = (const float*)d_in[2];
    const float* ln1w  = (const float*)d_in[3];
    const float* ln1b  = (const float*)d_in[4];
    const float* wqkv  = (const float*)d_in[5];
    const float* bqkv  = (const float*)d_in[6];
    const float* wproj = (const float*)d_in[7];
    const float* bproj = (const float*)d_in[8];
    const float* ln2w  = (const float*)d_in[9];
    const float* ln2b  = (const float*)d_in[10];
    const float* wfc1  = (const float*)d_in[11];
    const float* bfc1  = (const float*)d_in[12];
    const float* wfc2  = (const float*)d_in[13];
    const float* bfc2  = (const float*)d_in[14];
    float* out = (float*)d_out;

    float *xn1, *xn2, *qkv, *yv, *act, *wc;
    cudaGetSymbolAddress((void**)&xn1, g_xn1);
    cudaGetSymbolAddress((void**)&xn2, g_xn2);
    cudaGetSymbolAddress((void**)&qkv, g_qkv);
    cudaGetSymbolAddress((void**)&yv,  g_y);
    cudaGetSymbolAddress((void**)&act, g_act);
    cudaGetSymbolAddress((void**)&wc,  g_wcvt);
    float* wqkv_t  = wc;                 // [3072][2048]
    float* wproj_t = wc + 6291456;       // [2048][2048]
    float* wfc1_t  = wc + 10485760;      // [8192][2048]
    float* wfc2_t  = wc + 27262976;      // [2048][8192]

    // one-time stream/event creation (resources persist; no device memory)
    static cudaStream_t s1 = nullptr, s2 = nullptr;
    static cudaEvent_t eRoot, eLn, eQkv, eVt, eW2, eFc1;
    if (!s1) {
        cudaStreamCreateWithFlags(&s1, cudaStreamNonBlocking);
        cudaStreamCreateWithFlags(&s2, cudaStreamNonBlocking);
        cudaEventCreateWithFlags(&eRoot, cudaEventDisableTiming);
        cudaEventCreateWithFlags(&eLn,   cudaEventDisableTiming);
        cudaEventCreateWithFlags(&eQkv,  cudaEventDisableTiming);
        cudaEventCreateWithFlags(&eVt,   cudaEventDisableTiming);
        cudaEventCreateWithFlags(&eW2,   cudaEventDisableTiming);
        cudaEventCreateWithFlags(&eFc1,  cudaEventDisableTiming);
    }

    static bool attrs_set = false;
    if (!attrs_set) {
        cudaFuncSetAttribute(mm_pipe<EPI_CVT>,    cudaFuncAttributeMaxDynamicSharedMemorySize, MM_SMEM);
        cudaFuncSetAttribute(mm_pipe<EPI_RESID>,  cudaFuncAttributeMaxDynamicSharedMemorySize, MM_SMEM);
        cudaFuncSetAttribute(mm_pipe<EPI_GELU>,   cudaFuncAttributeMaxDynamicSharedMemorySize, MM_SMEM);
        cudaFuncSetAttribute(mm_pipe<EPI_ADDOUT>, cudaFuncAttributeMaxDynamicSharedMemorySize, MM_SMEM);
        cudaFuncSetAttribute(attn_scores_mma,     cudaFuncAttributeMaxDynamicSharedMemorySize, MM_SMEM);
        cudaFuncSetAttribute(attn_av_mma,         cudaFuncAttributeMaxDynamicSharedMemorySize, MM_SMEM);
        attrs_set = true;
    }

    // ---- fork root
    cudaEventRecord(eRoot, 0);
    cudaStreamWaitEvent(s1, eRoot, 0);
    cudaStreamWaitEvent(s2, eRoot, 0);

    // ---- s1: fc1 weight prep (independent), then fc1 after LN
    wtrans_kernel<<<dim3(FFN/32, CEMB/32), 256, 0, s1>>>(wfc1, wfc1_t, CEMB, FFN);

    // ---- s2: proj + fc2 weight prep (off critical path)
    wtrans_kernel<<<dim3(CEMB/32, CEMB/32), 256, 0, s2>>>(wproj, wproj_t, CEMB, CEMB);
    wtrans_kernel<<<dim3(CEMB/32, FFN/32),  256, 0, s2>>>(wfc2,  wfc2_t,  FFN,  CEMB);
    cudaEventRecord(eW2, s2);

    // ---- s0: LN -> (eLn) -> qkv weight prep -> QKV GEMM -> (eQkv)
    ln_kernel<<<MROWS, 256>>>(x, ln1w, ln1b, ln2w, ln2b);
    cudaEventRecord(eLn, 0);
    wtrans_kernel<<<dim3(QKVN/32, CEMB/32), 256>>>(wqkv, wqkv_t, CEMB, QKVN);
    mm_pipe<EPI_CVT><<<dim3(QKVN/128, MROWS/128), 256, MM_SMEM>>>(
        xn1, wqkv_t, qkv, QKVN, bqkv, nullptr, CEMB);
    cudaEventRecord(eQkv, 0);

    // ---- s1: fc1 GEMM + GELU (overlaps entire attention phase)
    cudaStreamWaitEvent(s1, eLn, 0);
    mm_pipe<EPI_GELU><<<dim3(FFN/128, MROWS/128), 256, MM_SMEM, s1>>>(
        xn2, wfc1_t, act, FFN, bfc1, nullptr, CEMB);
    cudaEventRecord(eFc1, s1);

    // ---- s2: V transpose (needs QKV only; concurrent with rope+scores)
    cudaStreamWaitEvent(s2, eQkv, 0);
    vtrans_kernel<<<dim3(TSEQ/32, HD/32, BATCH*NGRP), 256, 0, s2>>>();
    cudaEventRecord(eVt, s2);

    // ---- s0: rope -> scores -> (join vtrans) -> AV -> (join w2) -> proj
    rope_kernel<<<MROWS, 320>>>(cosb, sinb);
    attn_scores_mma<<<dim3(136, 1, BATCH*NHEAD), 256, MM_SMEM>>>();
    cudaStreamWaitEvent(0, eVt, 0);
    attn_av_mma<<<dim3(16, BATCH*NHEAD), 256, MM_SMEM>>>();
    cudaStreamWaitEvent(0, eW2, 0);
    mm_pipe<EPI_RESID><<<dim3(CEMB/128, MROWS/128), 256, MM_SMEM>>>(
        yv, wproj_t, out, CEMB, bproj, x, CEMB);

    // ---- s0: (join fc1) -> fc2 adds into out
    cudaStreamWaitEvent(0, eFc1, 0);
    mm_pipe<EPI_ADDOUT><<<dim3(CEMB/128, MROWS/128), 256, MM_SMEM>>>(
        act, wfc2_t, out, CEMB, bfc2, nullptr, FFN);
}